// round 9
// baseline (speedup 1.0000x reference)
#include <cuda_runtime.h>
#include <cuda_bf16.h>
#include <cstdint>

constexpr int B     = 8;
constexpr int HQ    = 32;
constexpr int HKV   = 8;
constexpr int G     = 4;
constexpr int D     = 128;
constexpr int BS    = 128;
constexpr int NCMPB = 16;
constexpr int NORIB = 64;
constexpr int NSPLIT = 16;
constexpr int PAGE_ELEMS = 2 * BS * HKV * D;
constexpr float SCALE  = 0.08838834764831845f;
constexpr float NEGINF = -1e30f;

// Dynamic SMEM layout: [ V tiles 64KB | acc 8KB | p 2KB ]
constexpr int SM_V_F4   = BS * 32;                 // 4096 float4 = 64 KB
constexpr int SM_ACC_F  = 4 * G * D;               // 2048 floats = 8 KB
constexpr int SM_P_F    = BS * G;                  // 512 floats  = 2 KB
constexpr int SMEM_BYTES = SM_V_F4 * 16 + SM_ACC_F * 4 + SM_P_F * 4;

// Allocation-free scratch
__device__ float  g_pacc[B * HKV * NSPLIT * G * D];  // 2 MB unnormalized partials
__device__ float  g_pm  [B * HKV * NSPLIT * G];
__device__ float  g_ps  [B * HKV * NSPLIT * G];
__device__ float  g_tl  [B * HKV * 3 * G];           // tail logits
__device__ float4 g_tv  [B * HKV * 3 * (D / 4)];     // tail V rows
__device__ int    g_cnt [B * HKV];                   // arrival counters (zero-init)

__device__ __forceinline__ void cp_async16(void* smem_dst, const void* gsrc) {
    uint32_t s = (uint32_t)__cvta_generic_to_shared(smem_dst);
    asm volatile("cp.async.cg.shared.global [%0], [%1], 16;\n" :: "r"(s), "l"(gsrc));
}
__device__ __forceinline__ void cp_async_commit() {
    asm volatile("cp.async.commit_group;\n" ::: "memory");
}
__device__ __forceinline__ void cp_async_wait_all() {
    asm volatile("cp.async.wait_group 0;\n" ::: "memory");
}

__device__ __forceinline__ float warp_sum(float v) {
    v += __shfl_xor_sync(0xffffffffu, v, 16);
    v += __shfl_xor_sync(0xffffffffu, v, 8);
    v += __shfl_xor_sync(0xffffffffu, v, 4);
    v += __shfl_xor_sync(0xffffffffu, v, 2);
    v += __shfl_xor_sync(0xffffffffu, v, 1);
    return v;
}
__device__ __forceinline__ float warp_max(float v) {
    v = fmaxf(v, __shfl_xor_sync(0xffffffffu, v, 16));
    v = fmaxf(v, __shfl_xor_sync(0xffffffffu, v, 8));
    v = fmaxf(v, __shfl_xor_sync(0xffffffffu, v, 4));
    v = fmaxf(v, __shfl_xor_sync(0xffffffffu, v, 2));
    v = fmaxf(v, __shfl_xor_sync(0xffffffffu, v, 1));
    return v;
}

// 4-head warp reduction in 11 shuffles.
__device__ __forceinline__ void reduce4(float x0, float x1, float x2, float x3,
                                        int l, float* dst /* &sm_p[t*4] */)
{
    x0 += __shfl_xor_sync(0xffffffffu, x0, 16);
    x1 += __shfl_xor_sync(0xffffffffu, x1, 16);
    x2 += __shfl_xor_sync(0xffffffffu, x2, 16);
    x3 += __shfl_xor_sync(0xffffffffu, x3, 16);
    x0 += __shfl_xor_sync(0xffffffffu, x0, 8);
    x1 += __shfl_xor_sync(0xffffffffu, x1, 8);
    x2 += __shfl_xor_sync(0xffffffffu, x2, 8);
    x3 += __shfl_xor_sync(0xffffffffu, x3, 8);
    const int g = l >> 3;
    float v = (g == 0) ? x0 : (g == 1) ? x1 : (g == 2) ? x2 : x3;
    v += __shfl_xor_sync(0xffffffffu, v, 4);
    v += __shfl_xor_sync(0xffffffffu, v, 2);
    v += __shfl_xor_sync(0xffffffffu, v, 1);
    if ((l & 7) == 0) dst[g] = v * SCALE;
}

__device__ __forceinline__ void fma_tok(float4* acc, float4 v4, float4 p4) {
    acc[0].x += p4.x * v4.x; acc[0].y += p4.x * v4.y;
    acc[0].z += p4.x * v4.z; acc[0].w += p4.x * v4.w;
    acc[1].x += p4.y * v4.x; acc[1].y += p4.y * v4.y;
    acc[1].z += p4.y * v4.z; acc[1].w += p4.y * v4.w;
    acc[2].x += p4.z * v4.x; acc[2].y += p4.z * v4.y;
    acc[2].z += p4.z * v4.z; acc[2].w += p4.z * v4.w;
    acc[3].x += p4.w * v4.x; acc[3].y += p4.w * v4.y;
    acc[3].z += p4.w * v4.z; acc[3].w += p4.w * v4.w;
}

// Merge: run by the last-arriving split CTA of (b, hkv). All inputs L2-hot.
__device__ __forceinline__ void merge_bh(int bh, int hkv,
    const float* __restrict__ sinks, float* __restrict__ out)
{
    const int tid  = threadIdx.x;
    const int base = bh * NSPLIT * G;
    const int b    = bh / HKV;

#pragma unroll
    for (int rep = 0; rep < 2; ++rep) {
        const int idx = rep * 256 + tid;          // 0..511
        const int g = idx >> 7, d = idx & 127;

        float pm[NSPLIT];
#pragma unroll
        for (int sp = 0; sp < NSPLIT; ++sp)
            pm[sp] = __ldcg(&g_pm[base + sp * G + g]);

        float tl[3];
#pragma unroll
        for (int t = 0; t < 3; ++t)
            tl[t] = __ldcg(&g_tl[(bh * 3 + t) * G + g]);

        const float sink = sinks[hkv * G + g];
        float M = sink;
#pragma unroll
        for (int sp = 0; sp < NSPLIT; ++sp) M = fmaxf(M, pm[sp]);
#pragma unroll
        for (int t = 0; t < 3; ++t) M = fmaxf(M, tl[t]);

        float S = __expf(sink - M);
        float num = 0.f;
#pragma unroll
        for (int sp = 0; sp < NSPLIT; ++sp) {
            const float w = __expf(pm[sp] - M);
            S += w * __ldcg(&g_ps[base + sp * G + g]);
            if (w > 0.f)
                num += w * __ldcg(&g_pacc[(size_t)(base + sp * G + g) * D + d]);
        }
        const float* tvf = (const float*)&g_tv[bh * 3 * (D / 4)];
#pragma unroll
        for (int t = 0; t < 3; ++t) {
            const float p = __expf(tl[t] - M);   // exactly 0 for invalid tail
            S   += p;
            num += p * tvf[t * D + d];
        }
        out[((size_t)b * HQ + hkv * G + g) * D + d] = num / S;
    }
}

// ---------------------------------------------------------------------------
// One CTA per (b, hkv, page). Pass 1 streams K via batched LDG while ALL of V
// (64 KB) flows into SMEM via cp.async. Pass 2 is pure SMEM FMA.
// ---------------------------------------------------------------------------
__global__ __launch_bounds__(256) void attn_kernel(
    const float* __restrict__ q,
    const float* __restrict__ cmp_kv,
    const int*   __restrict__ cmp_bt,
    const int*   __restrict__ seqused,
    const float* __restrict__ ori_kv,
    const int*   __restrict__ ori_bt,
    const float* __restrict__ sinks,
    float*       __restrict__ out)
{
    extern __shared__ __align__(16) unsigned char smem_raw[];
    float4* sm_v   = (float4*)smem_raw;                       // [BS][32] float4
    float*  sm_acc = (float*)(smem_raw + SM_V_F4 * 16);       // [4][G][D]
    float*  sm_p   = sm_acc + SM_ACC_F;                       // [BS][G]

    const int split = blockIdx.x % NSPLIT;
    const int bh    = blockIdx.x / NSPLIT;
    const int hkv   = bh % HKV;
    const int b     = bh / HKV;
    const int tid   = threadIdx.x;
    const int w     = tid >> 5;
    const int l     = tid & 31;

    const int seq     = seqused[b];
    const int cmp_len = seq >> 2;
    int cnt = cmp_len - split * BS;
    if (cnt > BS) cnt = BS;

    const int pmbase = (bh * NSPLIT + split) * G;

    if (cnt <= 0) {
        if (tid < G) { g_pm[pmbase + tid] = NEGINF; g_ps[pmbase + tid] = 0.f; }
    } else {
        const int page = cmp_bt[b * NCMPB + split];
        const float4* kbase = (const float4*)(cmp_kv + (size_t)page * PAGE_ELEMS + hkv * D);
        const float4* vbase = kbase + (BS * HKV * D) / 4;
        constexpr int TOKSTRIDE = HKV * D / 4;

        float4 qv[G];
        const float* qb = q + ((size_t)b * HQ + hkv * G) * D;
#pragma unroll
        for (int g = 0; g < G; ++g)
            qv[g] = ((const float4*)(qb + g * D))[l];

        // ---- pass 1: cp.async ALL V + batched K LDG + reduce4 ----
        if (cnt == BS) {
#pragma unroll
            for (int i = 0; i < 4; ++i) {
                // 4 V prefetches (independent, async)
#pragma unroll
                for (int j = 0; j < 4; ++j) {
                    const int t = w + (4 * i + j) * 8;
                    cp_async16(&sm_v[t * 32 + l], &vbase[(size_t)t * TOKSTRIDE + l]);
                }
                // 4 K loads front-batched
                float4 k4[4];
#pragma unroll
                for (int j = 0; j < 4; ++j) {
                    const int t = w + (4 * i + j) * 8;
                    k4[j] = kbase[(size_t)t * TOKSTRIDE + l];
                }
                // 4 independent reduction chains
#pragma unroll
                for (int j = 0; j < 4; ++j) {
                    const int t = w + (4 * i + j) * 8;
                    reduce4(qv[0].x*k4[j].x + qv[0].y*k4[j].y + qv[0].z*k4[j].z + qv[0].w*k4[j].w,
                            qv[1].x*k4[j].x + qv[1].y*k4[j].y + qv[1].z*k4[j].z + qv[1].w*k4[j].w,
                            qv[2].x*k4[j].x + qv[2].y*k4[j].y + qv[2].z*k4[j].z + qv[2].w*k4[j].w,
                            qv[3].x*k4[j].x + qv[3].y*k4[j].y + qv[3].z*k4[j].z + qv[3].w*k4[j].w,
                            l, &sm_p[t * G]);
                }
            }
        } else {
            for (int t = w; t < cnt; t += 8) {
                cp_async16(&sm_v[t * 32 + l], &vbase[(size_t)t * TOKSTRIDE + l]);
                const float4 k4 = kbase[(size_t)t * TOKSTRIDE + l];
                reduce4(qv[0].x*k4.x + qv[0].y*k4.y + qv[0].z*k4.z + qv[0].w*k4.w,
                        qv[1].x*k4.x + qv[1].y*k4.y + qv[1].z*k4.z + qv[1].w*k4.w,
                        qv[2].x*k4.x + qv[2].y*k4.y + qv[2].z*k4.z + qv[2].w*k4.w,
                        qv[3].x*k4.x + qv[3].y*k4.y + qv[3].z*k4.z + qv[3].w*k4.w,
                        l, &sm_p[t * G]);
            }
        }
        cp_async_commit();
        __syncthreads();

        // ---- block softmax numerators (warp g owns head g) ----
        if (w < G) {
            float vals[4];
            float mx = NEGINF;
#pragma unroll
            for (int i = 0; i < 4; ++i) {
                const int t = l + i * 32;
                vals[i] = (t < cnt) ? sm_p[t * G + w] : NEGINF;
                mx = fmaxf(mx, vals[i]);
            }
            mx = warp_max(mx);
            float s = 0.f;
#pragma unroll
            for (int i = 0; i < 4; ++i) {
                const int t = l + i * 32;
                if (t < cnt) {
                    const float p = __expf(vals[i] - mx);
                    s += p;
                    sm_p[t * G + w] = p;
                }
            }
            s = warp_sum(s);
            if (l == 0) { g_pm[pmbase + w] = mx; g_ps[pmbase + w] = s; }
        }
        cp_async_wait_all();
        __syncthreads();

        // ---- pass 2: V accumulate, entirely from SMEM ----
        float4 acc[G];
#pragma unroll
        for (int g = 0; g < G; ++g) acc[g] = make_float4(0.f, 0.f, 0.f, 0.f);

        if (cnt == BS) {
#pragma unroll
            for (int i = 0; i < BS / 8; ++i) {
                const int t = w + i * 8;
                fma_tok(acc, sm_v[t * 32 + l], *(const float4*)&sm_p[t * G]);
            }
        } else {
            for (int t = w; t < cnt; t += 8)
                fma_tok(acc, sm_v[t * 32 + l], *(const float4*)&sm_p[t * G]);
        }

        // ---- combine 8 warps via 4 buffers (warps 4-7 add into 0-3) ----
        if (w < 4) {
#pragma unroll
            for (int g = 0; g < G; ++g)
                ((float4*)(sm_acc + (w * G + g) * D))[l] = acc[g];
        }
        __syncthreads();
        if (w >= 4) {
#pragma unroll
            for (int g = 0; g < G; ++g) {
                float4* dp = &((float4*)(sm_acc + ((w - 4) * G + g) * D))[l];
                float4 x = *dp;
                x.x += acc[g].x; x.y += acc[g].y; x.z += acc[g].z; x.w += acc[g].w;
                *dp = x;
            }
        }
        __syncthreads();

        float* outp = g_pacc + (size_t)pmbase * D;
#pragma unroll
        for (int rep = 0; rep < 2; ++rep) {
            const int idx = rep * 256 + tid;
            const int g = idx >> 7, d = idx & 127;
            float v = sm_acc[(0 * G + g) * D + d] + sm_acc[(1 * G + g) * D + d]
                    + sm_acc[(2 * G + g) * D + d] + sm_acc[(3 * G + g) * D + d];
            outp[idx] = v;
        }

        // ---- split 0 also computes the <=3-token original-cache tail ----
        if (split == 0 && w < 3) {
            const int cmp_base = cmp_len << 2;
            const int ntail    = seq - cmp_base;     // 0..3
            float4* tvrow = &g_tv[(bh * 3 + w) * (D / 4)];
            if (w < ntail) {
                const int pos   = cmp_base + w;
                const int opage = ori_bt[b * NORIB + (pos >> 7)];
                const float* kp = ori_kv + (size_t)opage * PAGE_ELEMS
                                  + (size_t)(pos & 127) * HKV * D + hkv * D;
                const float4 k4 = ((const float4*)kp)[l];
                const float4 v4 = ((const float4*)(kp + BS * HKV * D))[l];
                tvrow[l] = v4;
#pragma unroll
                for (int g = 0; g < G; ++g) {
                    float x = qv[g].x * k4.x + qv[g].y * k4.y + qv[g].z * k4.z + qv[g].w * k4.w;
                    x = warp_sum(x);
                    if (l == g) g_tl[(bh * 3 + w) * G + g] = x * SCALE;
                }
            } else {
                if (l < G) g_tl[(bh * 3 + w) * G + l] = NEGINF;
                tvrow[l] = make_float4(0.f, 0.f, 0.f, 0.f);
            }
        }
    }

    // ---- last-CTA merge (threadFenceReduction pattern) ----
    __shared__ int s_last;
    __threadfence();
    if (tid == 0) {
        const int v = atomicAdd(&g_cnt[bh], 1);
        const int last = (v == NSPLIT - 1);
        if (last) g_cnt[bh] = 0;     // reset for next graph replay
        s_last = last;
    }
    __syncthreads();
    if (s_last) {
        __threadfence();
        merge_bh(bh, hkv, sinks, out);
    }
}

extern "C" void kernel_launch(void* const* d_in, const int* in_sizes, int n_in,
                              void* d_out, int out_size) {
    const float* q       = (const float*)d_in[0];
    const float* cmp_kv  = (const float*)d_in[1];
    const float* sinks   = (const float*)d_in[2];
    const int*   cmp_bt  = (const int*)d_in[3];
    const int*   seqused = (const int*)d_in[4];
    const float* ori_kv  = (const float*)d_in[5];
    const int*   ori_bt  = (const int*)d_in[6];
    float* out = (float*)d_out;

    static bool attr_set = false;
    if (!attr_set) {
        cudaFuncSetAttribute(attn_kernel,
                             cudaFuncAttributeMaxDynamicSharedMemorySize, SMEM_BYTES);
        attr_set = true;
    }

    attn_kernel<<<B * HKV * NSPLIT, 256, SMEM_BYTES>>>(q, cmp_kv, cmp_bt, seqused,
                                                       ori_kv, ori_bt, sinks, out);
}